// round 9
// baseline (speedup 1.0000x reference)
#include <cuda_runtime.h>
#include <cstdint>

// Problem: B=2, N=2048, C=1024, H=16, D=64
// g_q/g_v: [bh=32][n=2048][128], d 0..63 real, 64..127 imag (tf32-rounded)
// g_k:  same layout (proj output)
// g_k2: [bh=32][n=2048][192] = [kr(64) | ks=kr+ki (64) | kd=kr-ki (64)], tf32
// g_z: [b*2048+n][2048] = [out_r(1024) | out_i(1024)] (tf32-rounded)
// g_x, g_w: tf32-rounded copies of x and the 6 QKV weights
// g_wc, g_fb: combined output weight (tf32-rounded) and bias

#define PROJ_SMEM (2 * 2 * 128 * 36 * 4)                          // 73728 B
#define ATT_SMEM  ((2 * 32 * 196 + 2 * 32 * 136 + 64 * 36) * 4)   // 94208 B

__device__ float g_q[32 * 2048 * 128];
__device__ float g_k[32 * 2048 * 128];
__device__ float g_k2[32 * 2048 * 192];
__device__ float g_v[32 * 2048 * 128];
__device__ float g_z[4096 * 2048];
__device__ float g_x[4096 * 1024];
__device__ float g_w[6 * 1024 * 1024];
__device__ float g_wc[1024 * 2048];
__device__ float g_fb[1024];

// ---------------------------------------------------------------------------
// helpers
// ---------------------------------------------------------------------------
__device__ __forceinline__ float tf32f(float x) {
    uint32_t r;
    asm("cvt.rna.tf32.f32 %0, %1;" : "=r"(r) : "f"(x));
    return __int_as_float(r);
}
__device__ __forceinline__ uint32_t fu(float x) { return __float_as_uint(x); }

__device__ __forceinline__ float sqrt_ap(float x) {
    float r;
    asm("sqrt.approx.f32 %0, %1;" : "=f"(r) : "f"(x));
    return r;
}
__device__ __forceinline__ float ex2_ap(float x) {
    float r;
    asm("ex2.approx.f32 %0, %1;" : "=f"(r) : "f"(x));
    return r;
}

__device__ __forceinline__ void mma8(float* d,
                                     uint32_t a0, uint32_t a1, uint32_t a2, uint32_t a3,
                                     uint32_t b0, uint32_t b1) {
    asm volatile(
        "mma.sync.aligned.m16n8k8.row.col.f32.tf32.tf32.f32 "
        "{%0,%1,%2,%3}, {%4,%5,%6,%7}, {%8,%9}, {%0,%1,%2,%3};"
        : "+f"(d[0]), "+f"(d[1]), "+f"(d[2]), "+f"(d[3])
        : "r"(a0), "r"(a1), "r"(a2), "r"(a3), "r"(b0), "r"(b1));
}

__device__ __forceinline__ void cpa16(uint32_t dst, const float* src) {
    asm volatile("cp.async.cg.shared.global [%0], [%1], 16;" :: "r"(dst), "l"(src));
}
#define CP_COMMIT() asm volatile("cp.async.commit_group;")
#define CP_WAIT0()  asm volatile("cp.async.wait_group 0;")

// ---------------------------------------------------------------------------
// Pre-round x and the 6 QKV weights into g_x / g_w (tf32).
// ---------------------------------------------------------------------------
__global__ void __launch_bounds__(256) prep_kernel(
    const float* __restrict__ x,
    const float* __restrict__ qrw, const float* __restrict__ qiw,
    const float* __restrict__ krw, const float* __restrict__ kiw,
    const float* __restrict__ vrw, const float* __restrict__ viw)
{
    int i4 = blockIdx.x * 256 + threadIdx.x;
    const float* src;
    float* dst;
    if (i4 < 1048576) {
        src = x + (size_t)i4 * 4;
        dst = g_x + (size_t)i4 * 4;
    } else {
        int j = i4 - 1048576;
        int wsel = j >> 18;
        int off = j & 262143;
        const float* wp;
        switch (wsel) {
            case 0: wp = qrw; break;
            case 1: wp = qiw; break;
            case 2: wp = krw; break;
            case 3: wp = kiw; break;
            case 4: wp = vrw; break;
            default: wp = viw; break;
        }
        src = wp + (size_t)off * 4;
        dst = g_w + (size_t)wsel * 1048576 + (size_t)off * 4;
    }
    float4 v = *(const float4*)src;
    v.x = tf32f(v.x); v.y = tf32f(v.y); v.z = tf32f(v.z); v.w = tf32f(v.w);
    *(float4*)dst = v;
}

// ---------------------------------------------------------------------------
// Combined output weight (tf32-rounded) + bias.
// ---------------------------------------------------------------------------
__global__ void __launch_bounds__(256) make_wc_kernel(
    const float* __restrict__ orw, const float* __restrict__ oiw,
    const float* __restrict__ orb, const float* __restrict__ oib)
{
    int idx = blockIdx.x * 256 + threadIdx.x;
    int o = idx >> 9;
    int k = (idx & 511) << 2;
    float4 r;
    if (k < 1024) {
        float4 a = *(const float4*)(orw + (size_t)o * 1024 + k);
        float4 b = *(const float4*)(oiw + (size_t)o * 1024 + k);
        r.x = fmaf(0.1f, b.x, a.x); r.y = fmaf(0.1f, b.y, a.y);
        r.z = fmaf(0.1f, b.z, a.z); r.w = fmaf(0.1f, b.w, a.w);
    } else {
        int kk = k - 1024;
        float4 a = *(const float4*)(orw + (size_t)o * 1024 + kk);
        float4 b = *(const float4*)(oiw + (size_t)o * 1024 + kk);
        r.x = fmaf(0.1f, a.x, -b.x); r.y = fmaf(0.1f, a.y, -b.y);
        r.z = fmaf(0.1f, a.z, -b.z); r.w = fmaf(0.1f, a.w, -b.w);
    }
    r.x = tf32f(r.x); r.y = tf32f(r.y); r.z = tf32f(r.z); r.w = tf32f(r.w);
    *(float4*)(g_wc + (size_t)o * 2048 + k) = r;
    if ((idx & 511) == 0)
        g_fb[o] = 1.1f * orb[o] - 0.9f * oib[o];
}

// ---------------------------------------------------------------------------
// Augment K: g_k [row][kr|ki] -> g_k2 [row][kr | kr+ki | kr-ki] (tf32).
// 65536 rows x 16 float4 -> grid 4096 x 256.
// ---------------------------------------------------------------------------
__global__ void __launch_bounds__(256) kaug_kernel()
{
    int idx = blockIdx.x * 256 + threadIdx.x;
    int i4 = (idx & 15) * 4;
    int row = idx >> 4;
    const float* src = g_k + (size_t)row * 128 + i4;
    float4 kr = *(const float4*)src;
    float4 ki = *(const float4*)(src + 64);
    float* dst = g_k2 + (size_t)row * 192 + i4;
    *(float4*)dst = kr;
    float4 s = make_float4(tf32f(kr.x + ki.x), tf32f(kr.y + ki.y),
                           tf32f(kr.z + ki.z), tf32f(kr.w + ki.w));
    *(float4*)(dst + 64) = s;
    float4 d = make_float4(tf32f(kr.x - ki.x), tf32f(kr.y - ki.y),
                           tf32f(kr.z - ki.z), tf32f(kr.w - ki.w));
    *(float4*)(dst + 128) = d;
}

// ---------------------------------------------------------------------------
// Input projections: blockIdx.z = 0/1/2 -> Q/K/V.
// BM=128, BN=128, BK=32, cp.async double-buffered smem, tf32 mma.
// ---------------------------------------------------------------------------
__global__ void __launch_bounds__(256, 2) proj_mma_kernel(
    const float* __restrict__ qrb, const float* __restrict__ qib,
    const float* __restrict__ krb, const float* __restrict__ kib,
    const float* __restrict__ vrb, const float* __restrict__ vib)
{
    extern __shared__ float sm[];
    float* As = sm;                 // [2][128][36]
    float* Bs = sm + 2 * 128 * 36;  // [2][128][36]
    const uint32_t as_u = (uint32_t)__cvta_generic_to_shared(As);
    const uint32_t bs_u = (uint32_t)__cvta_generic_to_shared(Bs);

    const int t = threadIdx.x;
    const int w = t >> 5, lane = t & 31, g = lane >> 2, tg = lane & 3;
    const int wm = w >> 2, wn = w & 3;
    const int z = blockIdx.z;
    const int bx = blockIdx.x;
    const int m0 = blockIdx.y * 128;
    const bool imag = bx >= 8;
    const float* bias;
    float* Out;
    if (z == 0)      { bias = imag ? qib : qrb; Out = g_q; }
    else if (z == 1) { bias = imag ? kib : krb; Out = g_k; }
    else             { bias = imag ? vib : vrb; Out = g_v; }
    const float* W = g_w + (size_t)(z * 2 + (imag ? 1 : 0)) * 1024 * 1024;
    const int o0 = (bx & 7) * 128;

    int lr[4], lc[4];
    #pragma unroll
    for (int i = 0; i < 4; i++) { int idx = i * 256 + t; lr[i] = idx >> 3; lc[i] = (idx & 7) * 4; }

    const float* Ag = g_x + (size_t)m0 * 1024;
    const float* Bg = W + (size_t)o0 * 1024;

    auto loadAB = [&](int k0, int buf) {
        const int boff = buf * 128 * 36;
        #pragma unroll
        for (int i = 0; i < 4; i++) {
            cpa16(as_u + (boff + lr[i] * 36 + lc[i]) * 4, Ag + lr[i] * 1024 + k0 + lc[i]);
            cpa16(bs_u + (boff + lr[i] * 36 + lc[i]) * 4, Bg + lr[i] * 1024 + k0 + lc[i]);
        }
        CP_COMMIT();
    };

    float acc[4][4][4];
    #pragma unroll
    for (int a = 0; a < 4; a++)
        #pragma unroll
        for (int b = 0; b < 4; b++)
            #pragma unroll
            for (int c = 0; c < 4; c++) acc[a][b][c] = 0.f;

    loadAB(0, 0);

    for (int kt = 0; kt < 32; kt++) {
        CP_WAIT0();
        __syncthreads();
        if (kt + 1 < 32) loadAB((kt + 1) * 32, (kt + 1) & 1);
        const float* Ab = As + (kt & 1) * 128 * 36;
        const float* Bb = Bs + (kt & 1) * 128 * 36;
        #pragma unroll
        for (int ks = 0; ks < 4; ks++) {
            const int col = 8 * ks + tg;
            uint32_t a[4][4];
            #pragma unroll
            for (int mt = 0; mt < 4; mt++) {
                const float* ap = Ab + (64 * wm + 16 * mt + g) * 36;
                a[mt][0] = fu(ap[col]);
                a[mt][1] = fu(ap[8 * 36 + col]);
                a[mt][2] = fu(ap[col + 4]);
                a[mt][3] = fu(ap[8 * 36 + col + 4]);
            }
            #pragma unroll
            for (int nt = 0; nt < 4; nt++) {
                const float* bp = Bb + (32 * wn + 8 * nt + g) * 36;
                uint32_t b0 = fu(bp[col]);
                uint32_t b1 = fu(bp[col + 4]);
                #pragma unroll
                for (int mt = 0; mt < 4; mt++)
                    mma8(acc[mt][nt], a[mt][0], a[mt][1], a[mt][2], a[mt][3], b0, b1);
            }
        }
    }

    // epilogue: scatter tf32-rounded (acc + bias) into [bh][n][128]
    const int part = imag ? 1 : 0;
    const int ob = o0 + 32 * wn;
    const int hh = ob >> 6;
    #pragma unroll
    for (int mt = 0; mt < 4; mt++) {
        int m = m0 + 64 * wm + 16 * mt + g;
        #pragma unroll
        for (int r = 0; r < 2; r++) {
            int mm = m + 8 * r;
            int b_ = mm >> 11, nn = mm & 2047;
            float* dst = Out + ((size_t)(b_ * 16 + hh) * 2048 + nn) * 128 + part * 64;
            #pragma unroll
            for (int nt = 0; nt < 4; nt++) {
                int o = ob + 8 * nt + 2 * tg;
                float2 bv = *(const float2*)(bias + o);
                *(float2*)(dst + (o & 63)) =
                    make_float2(tf32f(acc[mt][nt][2 * r + 0] + bv.x),
                                tf32f(acc[mt][nt][2 * r + 1] + bv.y));
            }
        }
    }
}

// ---------------------------------------------------------------------------
// Fused complex-magnitude attention with Gauss 3-mma scores.
//   A1 += (qr+qi)·kr ; A2 += qr·(kr+ki) ; A3 += qi·(kr-ki)
//   sr = A1 - A3 ; si = A1 - A2
// Block = 64 queries x one bh; 4 warps; 32-key tiles; 2 CTAs/SM (94KB smem).
// Q fragments (qr, qi, qp=tf32(qr+qi)) in registers; K2/V cp.async dbl-buffered.
// Fixed-shift softmax: p = ex2(0.18034*|s| - 11.5416).
// ---------------------------------------------------------------------------
__global__ void __launch_bounds__(128, 2) attn_mma_kernel()
{
    extern __shared__ float sm[];
    float* Ks0 = sm;                   // [32][196]  (192 data + pad)
    float* Ks1 = sm + 32 * 196;        // [32][196]
    float* Vs0 = sm + 2 * 32 * 196;    // [32][136]
    float* Vs1 = Vs0 + 32 * 136;       // [32][136]
    float* Ps  = Vs1 + 32 * 136;       // [64][36]
    const uint32_t ks0_u = (uint32_t)__cvta_generic_to_shared(Ks0);
    const uint32_t ks1_u = (uint32_t)__cvta_generic_to_shared(Ks1);
    const uint32_t vs0_u = (uint32_t)__cvta_generic_to_shared(Vs0);
    const uint32_t vs1_u = (uint32_t)__cvta_generic_to_shared(Vs1);

    const int t = threadIdx.x;
    const int w = t >> 5, lane = t & 31, g = lane >> 2, tg = lane & 3;
    const int bh = blockIdx.y;
    const int q0 = blockIdx.x * 64;
    const int qrow = 16 * w;

    const float* Qg = g_q + ((size_t)bh * 2048 + q0) * 128;
    const float* Kg = g_k2 + (size_t)bh * 2048 * 192;
    const float* Vg = g_v + (size_t)bh * 2048 * 128;

    // stage Q (64 rows x 128, stride 132) at smem base
    #pragma unroll
    for (int i = 0; i < 16; i++) {
        int idx = i * 128 + t;
        int row = idx >> 5, c4 = (idx & 31) * 4;
        cpa16(ks0_u + (row * 132 + c4) * 4, Qg + row * 128 + c4);
    }
    CP_COMMIT();
    CP_WAIT0();
    __syncthreads();

    // Q fragments -> registers; qp = tf32(qr + qi)
    float qr[8][4], qi[8][4], qp[8][4];
    #pragma unroll
    for (int ks = 0; ks < 8; ks++) {
        const int col = 8 * ks + tg;
        const float* r0 = sm + (qrow + g) * 132;
        const float* r8 = sm + (qrow + g + 8) * 132;
        qr[ks][0] = r0[col];      qr[ks][1] = r8[col];
        qr[ks][2] = r0[col + 4];  qr[ks][3] = r8[col + 4];
        qi[ks][0] = r0[col + 64]; qi[ks][1] = r8[col + 64];
        qi[ks][2] = r0[col + 68]; qi[ks][3] = r8[col + 68];
        #pragma unroll
        for (int j = 0; j < 4; j++) qp[ks][j] = tf32f(qr[ks][j] + qi[ks][j]);
    }
    __syncthreads();   // done reading staged Q before K(0) overwrites

    auto loadKV = [&](int kt, uint32_t ku, uint32_t vu) {
        const float* Kt = Kg + (size_t)kt * 32 * 192;
        const float* Vt = Vg + (size_t)kt * 32 * 128;
        #pragma unroll
        for (int i = 0; i < 12; i++) {           // 32 rows x 48 f4 = 1536
            int idx = i * 128 + t;
            int row = idx / 48, c4 = (idx % 48) * 4;
            cpa16(ku + (row * 196 + c4) * 4, Kt + row * 192 + c4);
        }
        #pragma unroll
        for (int i = 0; i < 8; i++) {            // 32 rows x 32 f4 = 1024
            int idx = i * 128 + t;
            int row = idx >> 5, c4 = (idx & 31) * 4;
            cpa16(vu + (row * 136 + c4) * 4, Vt + row * 128 + c4);
        }
        CP_COMMIT();
    };

    float O[16][4];
    #pragma unroll
    for (int i = 0; i < 16; i++) { O[i][0] = 0.f; O[i][1] = 0.f; O[i][2] = 0.f; O[i][3] = 0.f; }
    float l0 = 0.f, l1 = 0.f;

    const float C1 = 0.18033688f;   // 0.125 * log2(e)
    const float C2 = -11.541560f;   // -8 * log2(e)

    loadKV(0, ks0_u, vs0_u);

    for (int kt = 0; kt < 64; kt++) {
        CP_WAIT0();
        __syncthreads();
        if (kt + 1 < 64)
            loadKV(kt + 1, (kt & 1) ? ks0_u : ks1_u, (kt & 1) ? vs0_u : vs1_u);
        const float* Kb = (kt & 1) ? Ks1 : Ks0;
        const float* Vb = (kt & 1) ? Vs1 : Vs0;

        float A1[4][4], A2[4][4], A3[4][4];
        #pragma unroll
        for (int i = 0; i < 4; i++)
            #pragma unroll
            for (int j = 0; j < 4; j++) { A1[i][j] = 0.f; A2[i][j] = 0.f; A3[i][j] = 0.f; }

        #pragma unroll 2
        for (int ks = 0; ks < 8; ks++) {
            const int col = 8 * ks + tg;
            const uint32_t ap0 = fu(qp[ks][0]), ap1 = fu(qp[ks][1]);
            const uint32_t ap2 = fu(qp[ks][2]), ap3 = fu(qp[ks][3]);
            const uint32_t ar0 = fu(qr[ks][0]), ar1 = fu(qr[ks][1]);
            const uint32_t ar2 = fu(qr[ks][2]), ar3 = fu(qr[ks][3]);
            const uint32_t ai0 = fu(qi[ks][0]), ai1 = fu(qi[ks][1]);
            const uint32_t ai2 = fu(qi[ks][2]), ai3 = fu(qi[ks][3]);
            #pragma unroll
            for (int nt = 0; nt < 4; nt++) {
                const float* kp = Kb + (8 * nt + g) * 196 + col;
                uint32_t br0 = fu(kp[0]);
                uint32_t br1 = fu(kp[4]);
                uint32_t bs0 = fu(kp[64]);
                uint32_t bs1 = fu(kp[68]);
                uint32_t bd0 = fu(kp[128]);
                uint32_t bd1 = fu(kp[132]);
                mma8(A1[nt], ap0, ap1, ap2, ap3, br0, br1);  // (qr+qi)·kr
                mma8(A2[nt], ar0, ar1, ar2, ar3, bs0, bs1);  // qr·(kr+ki)
                mma8(A3[nt], ai0, ai1, ai2, ai3, bd0, bd1);  // qi·(kr-ki)
            }
        }

        // sr = A1-A3, si = A1-A2; magnitude + exp via MUFU; accumulate l; store P
        #pragma unroll
        for (int nt = 0; nt < 4; nt++) {
            float sr0 = A1[nt][0] - A3[nt][0], si0 = A1[nt][0] - A2[nt][0];
            float sr1 = A1[nt][1] - A3[nt][1], si1 = A1[nt][1] - A2[nt][1];
            float sr2 = A1[nt][2] - A3[nt][2], si2 = A1[nt][2] - A2[nt][2];
            float sr3 = A1[nt][3] - A3[nt][3], si3 = A1[nt][3] - A2[nt][3];
            float h0 = fmaf(si0, si0, sr0 * sr0);
            float h1 = fmaf(si1, si1, sr1 * sr1);
            float h2 = fmaf(si2, si2, sr2 * sr2);
            float h3 = fmaf(si3, si3, sr3 * sr3);
            float p0 = ex2_ap(fmaf(sqrt_ap(h0), C1, C2));
            float p1 = ex2_ap(fmaf(sqrt_ap(h1), C1, C2));
            float p2 = ex2_ap(fmaf(sqrt_ap(h2), C1, C2));
            float p3 = ex2_ap(fmaf(sqrt_ap(h3), C1, C2));
            l0 += p0 + p1;
            l1 += p2 + p3;
            *(float2*)(Ps + (qrow + g) * 36 + 8 * nt + 2 * tg) = make_float2(tf32f(p0), tf32f(p1));
            *(float2*)(Ps + (qrow + g + 8) * 36 + 8 * nt + 2 * tg) = make_float2(tf32f(p2), tf32f(p3));
        }
        __syncwarp();   // each warp reads only its own 16 P rows

        // O += P @ [vr|vi]
        #pragma unroll
        for (int ks = 0; ks < 4; ks++) {
            const int pcol = 8 * ks + tg;
            uint32_t a0 = fu(Ps[(qrow + g) * 36 + pcol]);
            uint32_t a1 = fu(Ps[(qrow + g + 8) * 36 + pcol]);
            uint32_t a2 = fu(Ps[(qrow + g) * 36 + pcol + 4]);
            uint32_t a3 = fu(Ps[(qrow + g + 8) * 36 + pcol + 4]);
            const float* v0p = Vb + (8 * ks + tg) * 136 + g;
            const float* v1p = Vb + (8 * ks + tg + 4) * 136 + g;
            #pragma unroll
            for (int nt = 0; nt < 16; nt++) {
                uint32_t b0 = fu(v0p[8 * nt]);
                uint32_t b1 = fu(v1p[8 * nt]);
                mma8(O[nt], a0, a1, a2, a3, b0, b1);
            }
        }
    }

    // epilogue: divide by row sums, write tf32-rounded merged-head layout
    l0 += __shfl_xor_sync(0xffffffffu, l0, 1);
    l0 += __shfl_xor_sync(0xffffffffu, l0, 2);
    l1 += __shfl_xor_sync(0xffffffffu, l1, 1);
    l1 += __shfl_xor_sync(0xffffffffu, l1, 2);
    const float inv0 = 1.f / l0, inv1 = 1.f / l1;

    const int b_ = bh >> 4, hh = bh & 15;
    const int q = q0 + qrow + g;
    float* dst0 = g_z + (size_t)(b_ * 2048 + q) * 2048;
    float* dst1 = g_z + (size_t)(b_ * 2048 + q + 8) * 2048;
    #pragma unroll
    for (int nt = 0; nt < 16; nt++) {
        int d0 = 8 * nt + 2 * tg;
        int col = (d0 >> 6) * 1024 + hh * 64 + (d0 & 63);
        *(float2*)(dst0 + col) = make_float2(tf32f(O[nt][0] * inv0), tf32f(O[nt][1] * inv0));
        *(float2*)(dst1 + col) = make_float2(tf32f(O[nt][2] * inv1), tf32f(O[nt][3] * inv1));
    }
}

// ---------------------------------------------------------------------------
// Final GEMM: out[m][o] = sum_k g_z[m][k]*g_wc[o][k] + g_fb[o]
// M=4096, N=1024, K=2048. cp.async double-buffered.
// ---------------------------------------------------------------------------
__global__ void __launch_bounds__(256, 2) final_mma_kernel(float* __restrict__ Outp)
{
    extern __shared__ float sm[];
    float* As = sm;
    float* Bs = sm + 2 * 128 * 36;
    const uint32_t as_u = (uint32_t)__cvta_generic_to_shared(As);
    const uint32_t bs_u = (uint32_t)__cvta_generic_to_shared(Bs);

    const int t = threadIdx.x;
    const int w = t >> 5, lane = t & 31, g = lane >> 2, tg = lane & 3;
    const int wm = w >> 2, wn = w & 3;
    const int m0 = blockIdx.y * 128;
    const int o0 = blockIdx.x * 128;

    int lr[4], lc[4];
    #pragma unroll
    for (int i = 0; i < 4; i++) { int idx = i * 256 + t; lr[i] = idx >> 3; lc[i] = (idx & 7) * 4; }

    const float* Ag = g_z + (size_t)m0 * 2048;
    const float* Bg = g_wc + (size_t)o0 * 2048;

    auto loadAB = [&](int k0, int buf) {
        const int boff = buf * 128 * 36;
        #pragma unroll
        for (int i = 0; i < 4; i++) {
            cpa16(as_u + (boff + lr[i] * 36 + lc[i]) * 4, Ag + lr[i] * 2048 + k0 + lc[i]);
            cpa16(bs_u + (boff + lr[i] * 36 + lc[i]) * 4, Bg + lr[i] * 2048 + k0 + lc[i]);
        }
        CP_COMMIT();
    };

    float acc[4][4][4];
    #pragma unroll
    for (int a = 0; a < 4; a++)
        #pragma unroll
        for (int b = 0; b < 4; b++)
            #pragma unroll
            for (int c = 0; c < 4; c++) acc[a][b][c] = 0.f;

    loadAB(0, 0);

    for (int kt = 0; kt < 64; kt++) {
        CP_WAIT0();
        __syncthreads();
        if (kt + 1 < 64) loadAB((kt + 1) * 32, (kt + 1) & 1);
        const float* Ab = As + (kt & 1) * 128 * 36;
        const float* Bb = Bs + (kt & 1) * 128 * 36;
        #pragma unroll
        for (int ks = 0; ks < 4; ks++) {
            const int col = 8 * ks + tg;
            uint32_t a[4][4];
            #pragma unroll
            for (int mt = 0; mt < 4; mt++) {
                const float* ap = Ab + (64 * wm + 16 * mt + g) * 36;
                a[mt][0] = fu(ap[col]);
                a[mt][1] = fu(ap[8 * 36 + col]);
                a[mt][2] = fu(ap[col + 4]);
                a[mt][3] = fu(ap[8 * 36 + col + 4]);
            }
            #pragma unroll
            for (int nt = 0; nt < 4; nt++) {
                const float* bp = Bb + (32 * wn + 8 * nt + g) * 36;
                uint32_t b0 = fu(bp[col]);
                uint32_t b1 = fu(bp[col + 4]);
                #pragma unroll
                for (int mt = 0; mt < 4; mt++)
                    mma8(acc[mt][nt], a[mt][0], a[mt][1], a[mt][2], a[mt][3], b0, b1);
            }
        }
    }

    const int ob = o0 + 32 * wn;
    #pragma unroll
    for (int mt = 0; mt < 4; mt++) {
        int m = m0 + 64 * wm + 16 * mt + g;
        #pragma unroll
        for (int r = 0; r < 2; r++) {
            int mm = m + 8 * r;
            float* dst = Outp + (size_t)mm * 1024;
            #pragma unroll
            for (int nt = 0; nt < 4; nt++) {
                int o = ob + 8 * nt + 2 * tg;
                float2 fb = *(const float2*)(g_fb + o);
                *(float2*)(dst + o) =
                    make_float2(acc[mt][nt][2 * r + 0] + fb.x,
                                acc[mt][nt][2 * r + 1] + fb.y);
            }
        }
    }
}

// ---------------------------------------------------------------------------
extern "C" void kernel_launch(void* const* d_in, const int* in_sizes, int n_in,
                              void* d_out, int out_size)
{
    const float* x    = (const float*)d_in[0];
    const float* qr_w = (const float*)d_in[1];
    const float* qr_b = (const float*)d_in[2];
    const float* qi_w = (const float*)d_in[3];
    const float* qi_b = (const float*)d_in[4];
    const float* kr_w = (const float*)d_in[5];
    const float* kr_b = (const float*)d_in[6];
    const float* ki_w = (const float*)d_in[7];
    const float* ki_b = (const float*)d_in[8];
    const float* vr_w = (const float*)d_in[9];
    const float* vr_b = (const float*)d_in[10];
    const float* vi_w = (const float*)d_in[11];
    const float* vi_b = (const float*)d_in[12];
    const float* or_w = (const float*)d_in[13];
    const float* or_b = (const float*)d_in[14];
    const float* oi_w = (const float*)d_in[15];
    const float* oi_b = (const float*)d_in[16];
    float* out = (float*)d_out;

    static bool attr_set = false;
    if (!attr_set) {
        cudaFuncSetAttribute(proj_mma_kernel, cudaFuncAttributeMaxDynamicSharedMemorySize, PROJ_SMEM);
        cudaFuncSetAttribute(attn_mma_kernel, cudaFuncAttributeMaxDynamicSharedMemorySize, ATT_SMEM);
        cudaFuncSetAttribute(final_mma_kernel, cudaFuncAttributeMaxDynamicSharedMemorySize, PROJ_SMEM);
        attr_set = true;
    }

    prep_kernel<<<10240, 256>>>(x, qr_w, qi_w, kr_w, ki_w, vr_w, vi_w);
    make_wc_kernel<<<2048, 256>>>(or_w, oi_w, or_b, oi_b);

    proj_mma_kernel<<<dim3(16, 32, 3), 256, PROJ_SMEM>>>(
        qr_b, qi_b, kr_b, ki_b, vr_b, vi_b);

    kaug_kernel<<<4096, 256>>>();

    attn_mma_kernel<<<dim3(32, 32), 128, ATT_SMEM>>>();

    final_mma_kernel<<<dim3(8, 32), 256, PROJ_SMEM>>>(out);
}

// round 10
// speedup vs baseline: 1.1029x; 1.1029x over previous
#include <cuda_runtime.h>
#include <cstdint>

// Problem: B=2, N=2048, C=1024, H=16, D=64
// g_q/g_k/g_v: [bh=32][n=2048][128], d 0..63 real, 64..127 imag (tf32-rounded)
// g_z: [b*2048+n][2048] = [out_r(1024) | out_i(1024)] (tf32-rounded)
// g_x, g_w: tf32-rounded copies of x and the 6 QKV weights
// g_wc, g_fb: combined output weight (tf32-rounded) and bias

#define PROJ_SMEM (2 * 2 * 128 * 36 * 4)                      // 73728 B
#define ATT_SMEM  ((2 * 32 * 132 + 2 * 32 * 136 + 64 * 36) * 4)  // 77824 B

__device__ float g_q[32 * 2048 * 128];
__device__ float g_k[32 * 2048 * 128];
__device__ float g_v[32 * 2048 * 128];
__device__ float g_z[4096 * 2048];
__device__ float g_x[4096 * 1024];
__device__ float g_w[6 * 1024 * 1024];
__device__ float g_wc[1024 * 2048];
__device__ float g_fb[1024];

// ---------------------------------------------------------------------------
// helpers
// ---------------------------------------------------------------------------
__device__ __forceinline__ float tf32f(float x) {
    uint32_t r;
    asm("cvt.rna.tf32.f32 %0, %1;" : "=r"(r) : "f"(x));
    return __int_as_float(r);
}
__device__ __forceinline__ uint32_t fu(float x) { return __float_as_uint(x); }

__device__ __forceinline__ float sqrt_ap(float x) {
    float r;
    asm("sqrt.approx.f32 %0, %1;" : "=f"(r) : "f"(x));
    return r;
}
__device__ __forceinline__ float ex2_ap(float x) {
    float r;
    asm("ex2.approx.f32 %0, %1;" : "=f"(r) : "f"(x));
    return r;
}

__device__ __forceinline__ void mma8(float* d,
                                     uint32_t a0, uint32_t a1, uint32_t a2, uint32_t a3,
                                     uint32_t b0, uint32_t b1) {
    asm volatile(
        "mma.sync.aligned.m16n8k8.row.col.f32.tf32.tf32.f32 "
        "{%0,%1,%2,%3}, {%4,%5,%6,%7}, {%8,%9}, {%0,%1,%2,%3};"
        : "+f"(d[0]), "+f"(d[1]), "+f"(d[2]), "+f"(d[3])
        : "r"(a0), "r"(a1), "r"(a2), "r"(a3), "r"(b0), "r"(b1));
}

__device__ __forceinline__ void cpa16(uint32_t dst, const float* src) {
    asm volatile("cp.async.cg.shared.global [%0], [%1], 16;" :: "r"(dst), "l"(src));
}
#define CP_COMMIT() asm volatile("cp.async.commit_group;")
#define CP_WAIT0()  asm volatile("cp.async.wait_group 0;")
#define CP_WAIT1()  asm volatile("cp.async.wait_group 1;")
#define CP_WAIT2()  asm volatile("cp.async.wait_group 2;")

// ---------------------------------------------------------------------------
// Pre-round x and the 6 QKV weights into g_x / g_w (tf32).
// ---------------------------------------------------------------------------
__global__ void __launch_bounds__(256) prep_kernel(
    const float* __restrict__ x,
    const float* __restrict__ qrw, const float* __restrict__ qiw,
    const float* __restrict__ krw, const float* __restrict__ kiw,
    const float* __restrict__ vrw, const float* __restrict__ viw)
{
    int i4 = blockIdx.x * 256 + threadIdx.x;
    const float* src;
    float* dst;
    if (i4 < 1048576) {
        src = x + (size_t)i4 * 4;
        dst = g_x + (size_t)i4 * 4;
    } else {
        int j = i4 - 1048576;
        int wsel = j >> 18;
        int off = j & 262143;
        const float* wp;
        switch (wsel) {
            case 0: wp = qrw; break;
            case 1: wp = qiw; break;
            case 2: wp = krw; break;
            case 3: wp = kiw; break;
            case 4: wp = vrw; break;
            default: wp = viw; break;
        }
        src = wp + (size_t)off * 4;
        dst = g_w + (size_t)wsel * 1048576 + (size_t)off * 4;
    }
    float4 v = *(const float4*)src;
    v.x = tf32f(v.x); v.y = tf32f(v.y); v.z = tf32f(v.z); v.w = tf32f(v.w);
    *(float4*)dst = v;
}

// ---------------------------------------------------------------------------
// Combined output weight (tf32-rounded) + bias.
// ---------------------------------------------------------------------------
__global__ void __launch_bounds__(256) make_wc_kernel(
    const float* __restrict__ orw, const float* __restrict__ oiw,
    const float* __restrict__ orb, const float* __restrict__ oib)
{
    int idx = blockIdx.x * 256 + threadIdx.x;
    int o = idx >> 9;
    int k = (idx & 511) << 2;
    float4 r;
    if (k < 1024) {
        float4 a = *(const float4*)(orw + (size_t)o * 1024 + k);
        float4 b = *(const float4*)(oiw + (size_t)o * 1024 + k);
        r.x = fmaf(0.1f, b.x, a.x); r.y = fmaf(0.1f, b.y, a.y);
        r.z = fmaf(0.1f, b.z, a.z); r.w = fmaf(0.1f, b.w, a.w);
    } else {
        int kk = k - 1024;
        float4 a = *(const float4*)(orw + (size_t)o * 1024 + kk);
        float4 b = *(const float4*)(oiw + (size_t)o * 1024 + kk);
        r.x = fmaf(0.1f, a.x, -b.x); r.y = fmaf(0.1f, a.y, -b.y);
        r.z = fmaf(0.1f, a.z, -b.z); r.w = fmaf(0.1f, a.w, -b.w);
    }
    r.x = tf32f(r.x); r.y = tf32f(r.y); r.z = tf32f(r.z); r.w = tf32f(r.w);
    *(float4*)(g_wc + (size_t)o * 2048 + k) = r;
    if ((idx & 511) == 0)
        g_fb[o] = 1.1f * orb[o] - 0.9f * oib[o];
}

// ---------------------------------------------------------------------------
// Input projections: blockIdx.z = 0/1/2 -> Q/K/V.
// BM=128, BN=128, BK=32, cp.async double-buffered smem, tf32 mma.
// launch_bounds(256,2): <=128 regs -> 2 CTAs/SM.
// ---------------------------------------------------------------------------
__global__ void __launch_bounds__(256, 2) proj_mma_kernel(
    const float* __restrict__ qrb, const float* __restrict__ qib,
    const float* __restrict__ krb, const float* __restrict__ kib,
    const float* __restrict__ vrb, const float* __restrict__ vib)
{
    extern __shared__ float sm[];
    float* As = sm;                 // [2][128][36]
    float* Bs = sm + 2 * 128 * 36;  // [2][128][36]
    const uint32_t as_u = (uint32_t)__cvta_generic_to_shared(As);
    const uint32_t bs_u = (uint32_t)__cvta_generic_to_shared(Bs);

    const int t = threadIdx.x;
    const int w = t >> 5, lane = t & 31, g = lane >> 2, tg = lane & 3;
    const int wm = w >> 2, wn = w & 3;
    const int z = blockIdx.z;
    const int bx = blockIdx.x;
    const int m0 = blockIdx.y * 128;
    const bool imag = bx >= 8;
    const float* bias;
    float* Out;
    if (z == 0)      { bias = imag ? qib : qrb; Out = g_q; }
    else if (z == 1) { bias = imag ? kib : krb; Out = g_k; }
    else             { bias = imag ? vib : vrb; Out = g_v; }
    const float* W = g_w + (size_t)(z * 2 + (imag ? 1 : 0)) * 1024 * 1024;
    const int o0 = (bx & 7) * 128;

    int lr[4], lc[4];
    #pragma unroll
    for (int i = 0; i < 4; i++) { int idx = i * 256 + t; lr[i] = idx >> 3; lc[i] = (idx & 7) * 4; }

    const float* Ag = g_x + (size_t)m0 * 1024;
    const float* Bg = W + (size_t)o0 * 1024;

    auto loadAB = [&](int k0, int buf) {
        const int boff = buf * 128 * 36;
        #pragma unroll
        for (int i = 0; i < 4; i++) {
            cpa16(as_u + (boff + lr[i] * 36 + lc[i]) * 4, Ag + lr[i] * 1024 + k0 + lc[i]);
            cpa16(bs_u + (boff + lr[i] * 36 + lc[i]) * 4, Bg + lr[i] * 1024 + k0 + lc[i]);
        }
        CP_COMMIT();
    };

    float acc[4][4][4];
    #pragma unroll
    for (int a = 0; a < 4; a++)
        #pragma unroll
        for (int b = 0; b < 4; b++)
            #pragma unroll
            for (int c = 0; c < 4; c++) acc[a][b][c] = 0.f;

    loadAB(0, 0);

    for (int kt = 0; kt < 32; kt++) {
        CP_WAIT0();
        __syncthreads();
        if (kt + 1 < 32) loadAB((kt + 1) * 32, (kt + 1) & 1);
        const float* Ab = As + (kt & 1) * 128 * 36;
        const float* Bb = Bs + (kt & 1) * 128 * 36;
        #pragma unroll
        for (int ks = 0; ks < 4; ks++) {
            const int col = 8 * ks + tg;
            uint32_t a[4][4];
            #pragma unroll
            for (int mt = 0; mt < 4; mt++) {
                const float* ap = Ab + (64 * wm + 16 * mt + g) * 36;
                a[mt][0] = fu(ap[col]);
                a[mt][1] = fu(ap[8 * 36 + col]);
                a[mt][2] = fu(ap[col + 4]);
                a[mt][3] = fu(ap[8 * 36 + col + 4]);
            }
            #pragma unroll
            for (int nt = 0; nt < 4; nt++) {
                const float* bp = Bb + (32 * wn + 8 * nt + g) * 36;
                uint32_t b0 = fu(bp[col]);
                uint32_t b1 = fu(bp[col + 4]);
                #pragma unroll
                for (int mt = 0; mt < 4; mt++)
                    mma8(acc[mt][nt], a[mt][0], a[mt][1], a[mt][2], a[mt][3], b0, b1);
            }
        }
    }

    // epilogue: scatter tf32-rounded (acc + bias) into [bh][n][128]
    const int part = imag ? 1 : 0;
    const int ob = o0 + 32 * wn;
    const int hh = ob >> 6;
    #pragma unroll
    for (int mt = 0; mt < 4; mt++) {
        int m = m0 + 64 * wm + 16 * mt + g;
        #pragma unroll
        for (int r = 0; r < 2; r++) {
            int mm = m + 8 * r;
            int b_ = mm >> 11, nn = mm & 2047;
            float* dst = Out + ((size_t)(b_ * 16 + hh) * 2048 + nn) * 128 + part * 64;
            #pragma unroll
            for (int nt = 0; nt < 4; nt++) {
                int o = ob + 8 * nt + 2 * tg;
                float2 bv = *(const float2*)(bias + o);
                *(float2*)(dst + (o & 63)) =
                    make_float2(tf32f(acc[mt][nt][2 * r + 0] + bv.x),
                                tf32f(acc[mt][nt][2 * r + 1] + bv.y));
            }
        }
    }
}

// ---------------------------------------------------------------------------
// Fused complex-magnitude attention, tf32 mma + MUFU softmax.
// Block = 64 queries x one bh; 4 warps; 32-key tiles; 2 CTAs/SM (78KB smem).
// Q fragments in registers; K/V cp.async double-buffered with SPLIT commit
// groups: K(t) is waited on before S-mma, V(t) only before PV — the V load
// of tile t overlaps the whole S+softmax phase of tile t.
// Fixed-shift softmax: p = ex2(0.18034*|s| - 11.5416) == exp(0.125*|s| - 8).
// ---------------------------------------------------------------------------
__global__ void __launch_bounds__(128, 2) attn_mma_kernel()
{
    extern __shared__ float sm[];
    float* Ks0 = sm;                   // [32][132]
    float* Ks1 = sm + 32 * 132;        // [32][132]
    float* Vs0 = sm + 2 * 32 * 132;    // [32][136]
    float* Vs1 = Vs0 + 32 * 136;       // [32][136]
    float* Ps  = Vs1 + 32 * 136;       // [64][36]
    const uint32_t ks0_u = (uint32_t)__cvta_generic_to_shared(Ks0);
    const uint32_t ks1_u = (uint32_t)__cvta_generic_to_shared(Ks1);
    const uint32_t vs0_u = (uint32_t)__cvta_generic_to_shared(Vs0);
    const uint32_t vs1_u = (uint32_t)__cvta_generic_to_shared(Vs1);

    const int t = threadIdx.x;
    const int w = t >> 5, lane = t & 31, g = lane >> 2, tg = lane & 3;
    const int bh = blockIdx.y;
    const int q0 = blockIdx.x * 64;
    const int qrow = 16 * w;

    const float* Qg = g_q + ((size_t)bh * 2048 + q0) * 128;
    const float* Kg = g_k + (size_t)bh * 2048 * 128;
    const float* Vg = g_v + (size_t)bh * 2048 * 128;

    // stage Q (64 rows x 128, stride 132) through the K double-buffer area
    #pragma unroll
    for (int i = 0; i < 16; i++) {
        int idx = i * 128 + t;
        int row = idx >> 5, c4 = (idx & 31) * 4;
        cpa16(ks0_u + (row * 132 + c4) * 4, Qg + row * 128 + c4);
    }
    CP_COMMIT();
    CP_WAIT0();
    __syncthreads();

    // Q fragments -> registers
    float qr[8][4], qi[8][4];
    #pragma unroll
    for (int ks = 0; ks < 8; ks++) {
        const int col = 8 * ks + tg;
        const float* r0 = sm + (qrow + g) * 132;
        const float* r8 = sm + (qrow + g + 8) * 132;
        qr[ks][0] = r0[col];      qr[ks][1] = r8[col];
        qr[ks][2] = r0[col + 4];  qr[ks][3] = r8[col + 4];
        qi[ks][0] = r0[col + 64]; qi[ks][1] = r8[col + 64];
        qi[ks][2] = r0[col + 68]; qi[ks][3] = r8[col + 68];
    }
    __syncthreads();   // done reading staged Q before K(0) overwrites

    auto loadK = [&](int kt, uint32_t ku) {
        const float* Kt = Kg + (size_t)kt * 32 * 128;
        #pragma unroll
        for (int i = 0; i < 8; i++) {
            int idx = i * 128 + t;
            int row = idx >> 5, c4 = (idx & 31) * 4;
            cpa16(ku + (row * 132 + c4) * 4, Kt + row * 128 + c4);
        }
        CP_COMMIT();
    };
    auto loadV = [&](int kt, uint32_t vu) {
        const float* Vt = Vg + (size_t)kt * 32 * 128;
        #pragma unroll
        for (int i = 0; i < 8; i++) {
            int idx = i * 128 + t;
            int row = idx >> 5, c4 = (idx & 31) * 4;
            cpa16(vu + (row * 136 + c4) * 4, Vt + row * 128 + c4);
        }
        CP_COMMIT();
    };

    float O[16][4];
    #pragma unroll
    for (int i = 0; i < 16; i++) { O[i][0] = 0.f; O[i][1] = 0.f; O[i][2] = 0.f; O[i][3] = 0.f; }
    float l0 = 0.f, l1 = 0.f;

    const float K1 = 0.18033688f;   // 0.125 * log2(e)
    const float K2 = -11.541560f;   // -8 * log2(e)

    loadK(0, ks0_u);
    loadV(0, vs0_u);

    for (int kt = 0; kt < 64; kt++) {
        // K(t) must be in smem; V(t) may still be in flight (1 group allowed).
        CP_WAIT1();
        __syncthreads();
        if (kt + 1 < 64) {
            loadK(kt + 1, (kt & 1) ? ks0_u : ks1_u);
            loadV(kt + 1, (kt & 1) ? vs0_u : vs1_u);
        }
        const float* Kb = (kt & 1) ? Ks1 : Ks0;
        const float* Vb = (kt & 1) ? Vs1 : Vs0;

        float Sr[4][4], Si[4][4];
        #pragma unroll
        for (int i = 0; i < 4; i++) {
            Sr[i][0] = 0.f; Sr[i][1] = 0.f; Sr[i][2] = 0.f; Sr[i][3] = 0.f;
            Si[i][0] = 0.f; Si[i][1] = 0.f; Si[i][2] = 0.f; Si[i][3] = 0.f;
        }

        #pragma unroll 2
        for (int ks = 0; ks < 8; ks++) {
            const int col = 8 * ks + tg;
            const uint32_t ar0 = fu(qr[ks][0]), ar1 = fu(qr[ks][1]);
            const uint32_t ar2 = fu(qr[ks][2]), ar3 = fu(qr[ks][3]);
            const uint32_t ai0 = fu(qi[ks][0]), ai1 = fu(qi[ks][1]);
            const uint32_t ai2 = fu(qi[ks][2]), ai3 = fu(qi[ks][3]);
            const uint32_t nr0 = ar0 ^ 0x80000000u, nr1 = ar1 ^ 0x80000000u;
            const uint32_t nr2 = ar2 ^ 0x80000000u, nr3 = ar3 ^ 0x80000000u;
            #pragma unroll
            for (int nt = 0; nt < 4; nt++) {
                const float* kp = Kb + (8 * nt + g) * 132 + col;
                uint32_t br0 = fu(kp[0]);
                uint32_t br1 = fu(kp[4]);
                uint32_t bi0 = fu(kp[64]);
                uint32_t bi1 = fu(kp[68]);
                mma8(Sr[nt], ar0, ar1, ar2, ar3, br0, br1);  // qr.kr
                mma8(Sr[nt], ai0, ai1, ai2, ai3, bi0, bi1);  // + qi.ki
                mma8(Si[nt], ai0, ai1, ai2, ai3, br0, br1);  // qi.kr
                mma8(Si[nt], nr0, nr1, nr2, nr3, bi0, bi1);  // - qr.ki
            }
        }

        // magnitude + exp via MUFU; accumulate l; store P
        #pragma unroll
        for (int nt = 0; nt < 4; nt++) {
            float h0 = fmaf(Si[nt][0], Si[nt][0], Sr[nt][0] * Sr[nt][0]);
            float h1 = fmaf(Si[nt][1], Si[nt][1], Sr[nt][1] * Sr[nt][1]);
            float h2 = fmaf(Si[nt][2], Si[nt][2], Sr[nt][2] * Sr[nt][2]);
            float h3 = fmaf(Si[nt][3], Si[nt][3], Sr[nt][3] * Sr[nt][3]);
            float p0 = ex2_ap(fmaf(sqrt_ap(h0), K1, K2));
            float p1 = ex2_ap(fmaf(sqrt_ap(h1), K1, K2));
            float p2 = ex2_ap(fmaf(sqrt_ap(h2), K1, K2));
            float p3 = ex2_ap(fmaf(sqrt_ap(h3), K1, K2));
            l0 += p0 + p1;
            l1 += p2 + p3;
            *(float2*)(Ps + (qrow + g) * 36 + 8 * nt + 2 * tg) = make_float2(tf32f(p0), tf32f(p1));
            *(float2*)(Ps + (qrow + g + 8) * 36 + 8 * nt + 2 * tg) = make_float2(tf32f(p2), tf32f(p3));
        }
        __syncwarp();   // each warp reads only its own 16 P rows

        // V(t) must be in smem now; K(t+1)/V(t+1) may still be pending (2 groups).
        CP_WAIT2();
        __syncthreads();

        // O += P @ [vr|vi]
        #pragma unroll
        for (int ks = 0; ks < 4; ks++) {
            const int pcol = 8 * ks + tg;
            uint32_t a0 = fu(Ps[(qrow + g) * 36 + pcol]);
            uint32_t a1 = fu(Ps[(qrow + g + 8) * 36 + pcol]);
            uint32_t a2 = fu(Ps[(qrow + g) * 36 + pcol + 4]);
            uint32_t a3 = fu(Ps[(qrow + g + 8) * 36 + pcol + 4]);
            const float* v0p = Vb + (8 * ks + tg) * 136 + g;
            const float* v1p = Vb + (8 * ks + tg + 4) * 136 + g;
            #pragma unroll
            for (int nt = 0; nt < 16; nt++) {
                uint32_t b0 = fu(v0p[8 * nt]);
                uint32_t b1 = fu(v1p[8 * nt]);
                mma8(O[nt], a0, a1, a2, a3, b0, b1);
            }
        }
    }

    // epilogue: divide by row sums, write tf32-rounded merged-head layout
    l0 += __shfl_xor_sync(0xffffffffu, l0, 1);
    l0 += __shfl_xor_sync(0xffffffffu, l0, 2);
    l1 += __shfl_xor_sync(0xffffffffu, l1, 1);
    l1 += __shfl_xor_sync(0xffffffffu, l1, 2);
    const float inv0 = 1.f / l0, inv1 = 1.f / l1;

    const int b_ = bh >> 4, hh = bh & 15;
    const int q = q0 + qrow + g;
    float* dst0 = g_z + (size_t)(b_ * 2048 + q) * 2048;
    float* dst1 = g_z + (size_t)(b_ * 2048 + q + 8) * 2048;
    #pragma unroll
    for (int nt = 0; nt < 16; nt++) {
        int d0 = 8 * nt + 2 * tg;
        int col = (d0 >> 6) * 1024 + hh * 64 + (d0 & 63);
        *(float2*)(dst0 + col) = make_float2(tf32f(O[nt][0] * inv0), tf32f(O[nt][1] * inv0));
        *(float2*)(dst1 + col) = make_float2(tf32f(O[nt][2] * inv1), tf32f(O[nt][3] * inv1));
    }
}

// ---------------------------------------------------------------------------
// Final GEMM: out[m][o] = sum_k g_z[m][k]*g_wc[o][k] + g_fb[o]
// M=4096, N=1024, K=2048. cp.async double-buffered.
// ---------------------------------------------------------------------------
__global__ void __launch_bounds__(256, 2) final_mma_kernel(float* __restrict__ Outp)
{
    extern __shared__ float sm[];
    float* As = sm;
    float* Bs = sm + 2 * 128 * 36;
    const uint32_t as_u = (uint32_t)__cvta_generic_to_shared(As);
    const uint32_t bs_u = (uint32_t)__cvta_generic_to_shared(Bs);

    const int t = threadIdx.x;
    const int w = t >> 5, lane = t & 31, g = lane >> 2, tg = lane & 3;
    const int wm = w >> 2, wn = w & 3;
    const int m0 = blockIdx.y * 128;
    const int o0 = blockIdx.x * 128;

    int lr[4], lc[4];
    #pragma unroll
    for (int i = 0; i < 4; i++) { int idx = i * 256 + t; lr[i] = idx >> 3; lc[i] = (idx & 7) * 4; }

    const float* Ag = g_z + (size_t)m0 * 2048;
    const float* Bg = g_wc + (size_t)o0 * 2048;

    auto loadAB = [&](int k0, int buf) {
        const int boff = buf * 128 * 36;
        #pragma unroll
        for (int i = 0; i < 4; i++) {
            cpa16(as_u + (boff + lr[i] * 36 + lc[i]) * 4, Ag + lr[i] * 2048 + k0 + lc[i]);
            cpa16(bs_u + (boff + lr[i] * 36 + lc[i]) * 4, Bg + lr[i] * 2048 + k0 + lc[i]);
        }
        CP_COMMIT();
    };

    float acc[4][4][4];
    #pragma unroll
    for (int a = 0; a < 4; a++)
        #pragma unroll
        for (int b = 0; b < 4; b++)
            #pragma unroll
            for (int c = 0; c < 4; c++) acc[a][b][c] = 0.f;

    loadAB(0, 0);

    for (int kt = 0; kt < 64; kt++) {
        CP_WAIT0();
        __syncthreads();
        if (kt + 1 < 64) loadAB((kt + 1) * 32, (kt + 1) & 1);
        const float* Ab = As + (kt & 1) * 128 * 36;
        const float* Bb = Bs + (kt & 1) * 128 * 36;
        #pragma unroll
        for (int ks = 0; ks < 4; ks++) {
            const int col = 8 * ks + tg;
            uint32_t a[4][4];
            #pragma unroll
            for (int mt = 0; mt < 4; mt++) {
                const float* ap = Ab + (64 * wm + 16 * mt + g) * 36;
                a[mt][0] = fu(ap[col]);
                a[mt][1] = fu(ap[8 * 36 + col]);
                a[mt][2] = fu(ap[col + 4]);
                a[mt][3] = fu(ap[8 * 36 + col + 4]);
            }
            #pragma unroll
            for (int nt = 0; nt < 4; nt++) {
                const float* bp = Bb + (32 * wn + 8 * nt + g) * 36;
                uint32_t b0 = fu(bp[col]);
                uint32_t b1 = fu(bp[col + 4]);
                #pragma unroll
                for (int mt = 0; mt < 4; mt++)
                    mma8(acc[mt][nt], a[mt][0], a[mt][1], a[mt][2], a[mt][3], b0, b1);
            }
        }
    }

    const int ob = o0 + 32 * wn;
    #pragma unroll
    for (int mt = 0; mt < 4; mt++) {
        int m = m0 + 64 * wm + 16 * mt + g;
        #pragma unroll
        for (int r = 0; r < 2; r++) {
            int mm = m + 8 * r;
            float* dst = Outp + (size_t)mm * 1024;
            #pragma unroll
            for (int nt = 0; nt < 4; nt++) {
                int o = ob + 8 * nt + 2 * tg;
                float2 fb = *(const float2*)(g_fb + o);
                *(float2*)(dst + o) =
                    make_float2(acc[mt][nt][2 * r + 0] + fb.x,
                                acc[mt][nt][2 * r + 1] + fb.y);
            }
        }
    }
}

// ---------------------------------------------------------------------------
extern "C" void kernel_launch(void* const* d_in, const int* in_sizes, int n_in,
                              void* d_out, int out_size)
{
    const float* x    = (const float*)d_in[0];
    const float* qr_w = (const float*)d_in[1];
    const float* qr_b = (const float*)d_in[2];
    const float* qi_w = (const float*)d_in[3];
    const float* qi_b = (const float*)d_in[4];
    const float* kr_w = (const float*)d_in[5];
    const float* kr_b = (const float*)d_in[6];
    const float* ki_w = (const float*)d_in[7];
    const float* ki_b = (const float*)d_in[8];
    const float* vr_w = (const float*)d_in[9];
    const float* vr_b = (const float*)d_in[10];
    const float* vi_w = (const float*)d_in[11];
    const float* vi_b = (const float*)d_in[12];
    const float* or_w = (const float*)d_in[13];
    const float* or_b = (const float*)d_in[14];
    const float* oi_w = (const float*)d_in[15];
    const float* oi_b = (const float*)d_in[16];
    float* out = (float*)d_out;

    static bool attr_set = false;
    if (!attr_set) {
        cudaFuncSetAttribute(proj_mma_kernel, cudaFuncAttributeMaxDynamicSharedMemorySize, PROJ_SMEM);
        cudaFuncSetAttribute(attn_mma_kernel, cudaFuncAttributeMaxDynamicSharedMemorySize, ATT_SMEM);
        cudaFuncSetAttribute(final_mma_kernel, cudaFuncAttributeMaxDynamicSharedMemorySize, PROJ_SMEM);
        attr_set = true;
    }

    prep_kernel<<<10240, 256>>>(x, qr_w, qi_w, kr_w, ki_w, vr_w, vi_w);
    make_wc_kernel<<<2048, 256>>>(or_w, oi_w, or_b, oi_b);

    proj_mma_kernel<<<dim3(16, 32, 3), 256, PROJ_SMEM>>>(
        qr_b, qi_b, kr_b, ki_b, vr_b, vi_b);

    attn_mma_kernel<<<dim3(32, 32), 128, ATT_SMEM>>>();

    final_mma_kernel<<<dim3(8, 32), 256, PROJ_SMEM>>>(out);
}